// round 10
// baseline (speedup 1.0000x reference)
#include <cuda_runtime.h>

// Fused bilinear 2x up -> leaky_relu(0.01) -> bilinear 0.5x down == 3x3 stencil.
// x, out: (16, 128, 128, 128) fp32 NHWC.
//
// R9 vs R7 (47.7us kernel, ~36us of pure FFMA issue at rt=2):
//  - all elementwise fp32 math rewritten as packed f32x2 (FFMA2/FADD2/FMUL2
//    via PTX; sm_100+ only) -> fma-pipe instruction count halved
//  - |u| for the leaky-sum identity via 64-bit AND mask on the idle alu pipe
//  - same structure/occupancy as R7: 3 CTAs, 2-row blocking, batched loads

constexpr int H   = 128;
constexpr int W   = 128;
constexpr int C4  = 32;    // 128 channels / 4  (one ulonglong2 = 4 floats)
constexpr int WC4 = W * C4;
constexpr int STRIP = 8;   // output columns per thread

using u64 = unsigned long long;
constexpr u64 ABSM = 0x7FFFFFFF7FFFFFFFULL;   // clears both sign bits

__device__ __forceinline__ u64 f2mul(u64 a, u64 b) {
    u64 d; asm("mul.rn.f32x2 %0, %1, %2;" : "=l"(d) : "l"(a), "l"(b)); return d;
}
__device__ __forceinline__ u64 f2add(u64 a, u64 b) {
    u64 d; asm("add.rn.f32x2 %0, %1, %2;" : "=l"(d) : "l"(a), "l"(b)); return d;
}
__device__ __forceinline__ u64 f2fma(u64 a, u64 b, u64 c) {
    u64 d; asm("fma.rn.f32x2 %0, %1, %2, %3;" : "=l"(d) : "l"(a), "l"(b), "l"(c)); return d;
}
__device__ __forceinline__ u64 pk(float f) {   // broadcast f into both halves
    unsigned u = __float_as_uint(f);
    return ((u64)u << 32) | u;
}

// L = 0.25*a + 0.75*b ; R = 0.75*b + 0.25*c   (packed, 2 pairs per float4)
__device__ __forceinline__ void hlerp2(const ulonglong2& a, const ulonglong2& b,
                                       const ulonglong2& c, ulonglong2& L, ulonglong2& R,
                                       u64 C34, u64 C14) {
    u64 tx = f2mul(b.x, C34), ty = f2mul(b.y, C34);
    L.x = f2fma(a.x, C14, tx); L.y = f2fma(a.y, C14, ty);
    R.x = f2fma(c.x, C14, tx); R.y = f2fma(c.y, C14, ty);
}

// U0 = 0.25*v0 + 0.75*v1 ; U1 = 0.75*v1 + 0.25*v2
__device__ __forceinline__ void vlerp2(const ulonglong2& v0, const ulonglong2& v1,
                                       const ulonglong2& v2, ulonglong2& U0, ulonglong2& U1,
                                       u64 C34, u64 C14) {
    u64 tx = f2mul(v1.x, C34), ty = f2mul(v1.y, C34);
    U0.x = f2fma(v0.x, C14, tx); U0.y = f2fma(v0.y, C14, ty);
    U1.x = f2fma(v2.x, C14, tx); U1.y = f2fma(v2.y, C14, ty);
}

// out = 0.25 * sum_k leaky(u_k)  ==  0.12625*sum(u) + 0.12375*sum(|u|)
__device__ __forceinline__ ulonglong2 corner2(const ulonglong2& u00, const ulonglong2& u01,
                                              const ulonglong2& u10, const ulonglong2& u11,
                                              u64 CSU, u64 CSA) {
    ulonglong2 r;
    {
        u64 su = f2add(f2add(u00.x, u01.x), f2add(u10.x, u11.x));
        u64 sa = f2add(f2add(u00.x & ABSM, u01.x & ABSM),
                       f2add(u10.x & ABSM, u11.x & ABSM));
        r.x = f2fma(su, CSU, f2mul(sa, CSA));
    }
    {
        u64 su = f2add(f2add(u00.y, u01.y), f2add(u10.y, u11.y));
        u64 sa = f2add(f2add(u00.y & ABSM, u01.y & ABSM),
                       f2add(u10.y & ABSM, u11.y & ABSM));
        r.y = f2fma(su, CSU, f2mul(sa, CSA));
    }
    return r;
}

__global__ __launch_bounds__(256, 3)
void activation_filter_kernel(const ulonglong2* __restrict__ x, ulonglong2* __restrict__ out) {
    const int r0 = 2 * blockIdx.x;     // output row pair (r0, r0+1 = +WC4 elems)
    const int half = blockIdx.y;       // width half (0: cols 0..63, 1: 64..127)
    const int b  = blockIdx.z;
    const int tid = threadIdx.x;
    const int c4    = tid & 31;
    const int strip = tid >> 5;        // 0..7, warp-uniform
    const int j0    = half * 64 + strip * STRIP;

    const u64 C34 = pk(0.75f),    C14 = pk(0.25f);
    const u64 CSU = pk(0.12625f), CSA = pk(0.12375f);

    const int im = (r0 > 0)         ? r0 - 1 : 0;      // row above r0 (clamped)
    const int iq = (r0 + 1 < H - 1) ? r0 + 2 : H - 1;  // row below r1 (clamped)

    const int img   = b * (H * WC4);
    const int basec = j0 * C4 + c4;
    const ulonglong2* __restrict__ pm = x + img + im * WC4 + basec;  // row im
    const ulonglong2* __restrict__ p0 = x + img + r0 * WC4 + basec;  // rows r0 (+WC4 -> r1)
    const ulonglong2* __restrict__ pq = x + img + iq * WC4 + basec;  // row iq
    ulonglong2* __restrict__ po = out + img + r0 * WC4 + basec;      // rows r0 (+WC4 -> r1)

    // window prologue: a = col j0-1 (clamped, warp-uniform), b = col j0
    const int offA = (j0 > 0) ? -C4 : 0;
    ulonglong2 a0 = pm[offA], a1 = p0[offA], a2 = p0[offA + WC4], a3 = pq[offA];
    ulonglong2 b0 = pm[0],    b1 = p0[0],    b2 = p0[WC4],        b3 = pq[0];

    #pragma unroll
    for (int s = 0; s < STRIP - 1; ++s) {
        // all loads first: 4 independent LDG.128
        ulonglong2 c0 = pm[C4];
        ulonglong2 c1 = p0[C4];
        ulonglong2 c2 = p0[C4 + WC4];
        ulonglong2 c3 = pq[C4];

        ulonglong2 L0, R0, L1, R1, L2, R2;
        hlerp2(a0, b0, c0, L0, R0, C34, C14); a0 = b0; b0 = c0;
        hlerp2(a1, b1, c1, L1, R1, C34, C14); a1 = b1; b1 = c1;
        hlerp2(a2, b2, c2, L2, R2, C34, C14); a2 = b2; b2 = c2;

        // finish output row r0 before touching row 3 (liveness)
        {
            ulonglong2 u00, u10, u01, u11;
            vlerp2(L0, L1, L2, u00, u10, C34, C14);
            vlerp2(R0, R1, R2, u01, u11, C34, C14);
            __stcs(po, corner2(u00, u01, u10, u11, CSU, CSA));
        }

        ulonglong2 L3, R3;
        hlerp2(a3, b3, c3, L3, R3, C34, C14); a3 = b3; b3 = c3;
        {
            ulonglong2 u00, u10, u01, u11;
            vlerp2(L1, L2, L3, u00, u10, C34, C14);
            vlerp2(R1, R2, R3, u01, u11, C34, C14);
            __stcs(po + WC4, corner2(u00, u01, u10, u11, CSU, CSA));
        }

        pm += C4; p0 += C4; pq += C4; po += C4;
    }

    // final column of the strip: only the rightmost strip clamps (warp-uniform)
    {
        ulonglong2 c0, c1, c2, c3;
        if (j0 + STRIP < W) {
            c0 = pm[C4]; c1 = p0[C4]; c2 = p0[C4 + WC4]; c3 = pq[C4];
        } else {
            c0 = b0; c1 = b1; c2 = b2; c3 = b3;
        }
        ulonglong2 L0, R0, L1, R1, L2, R2;
        hlerp2(a0, b0, c0, L0, R0, C34, C14);
        hlerp2(a1, b1, c1, L1, R1, C34, C14);
        hlerp2(a2, b2, c2, L2, R2, C34, C14);
        {
            ulonglong2 u00, u10, u01, u11;
            vlerp2(L0, L1, L2, u00, u10, C34, C14);
            vlerp2(R0, R1, R2, u01, u11, C34, C14);
            __stcs(po, corner2(u00, u01, u10, u11, CSU, CSA));
        }
        ulonglong2 L3, R3;
        hlerp2(a3, b3, c3, L3, R3, C34, C14);
        {
            ulonglong2 u00, u10, u01, u11;
            vlerp2(L1, L2, L3, u00, u10, C34, C14);
            vlerp2(R1, R2, R3, u01, u11, C34, C14);
            __stcs(po + WC4, corner2(u00, u01, u10, u11, CSU, CSA));
        }
    }
}

extern "C" void kernel_launch(void* const* d_in, const int* in_sizes, int n_in,
                              void* d_out, int out_size) {
    const ulonglong2* x = (const ulonglong2*)d_in[0];
    ulonglong2* out = (ulonglong2*)d_out;
    dim3 grid(H / 2, 2, 16);   // (row pair, width half, batch) = 2048 blocks
    activation_filter_kernel<<<grid, 256>>>(x, out);
}

// round 11
// speedup vs baseline: 1.0523x; 1.0523x over previous
#include <cuda_runtime.h>

// Fused bilinear 2x up -> leaky_relu(0.01) -> bilinear 0.5x down == 3x3 stencil.
// x, out: (16, 128, 128, 128) fp32 NHWC.
//
// R10 = R7 structure (best: 47.7us kernel; 3 CTAs, 2-row blocking, batched
// loads, pointer dedup) with corner_sum flattened into a single FFMA-imm
// chain: 0.12625*sum(u) + 0.12375*sum(|u|) as 1 FMUL-imm + 7 FFMA-imm
// (rt=1) instead of 6 FADD (rt=2) + FMUL + FFMA. R9's f32x2 packing is
// reverted (no fma-cycle win, +alu MOV overhead).

constexpr int H   = 128;
constexpr int W   = 128;
constexpr int C4  = 32;    // 128 channels / 4
constexpr int WC4 = W * C4;
constexpr int STRIP = 8;   // output columns per thread

// L = 0.25*a + 0.75*b ; R = 0.75*b + 0.25*c  (t = 0.75*b shared; FFMA-imm)
__device__ __forceinline__ void hlerp(const float4& a, const float4& b, const float4& c,
                                      float4& L, float4& R) {
    float tx = 0.75f * b.x, ty = 0.75f * b.y, tz = 0.75f * b.z, tw = 0.75f * b.w;
    L = make_float4(fmaf(a.x, 0.25f, tx), fmaf(a.y, 0.25f, ty),
                    fmaf(a.z, 0.25f, tz), fmaf(a.w, 0.25f, tw));
    R = make_float4(fmaf(c.x, 0.25f, tx), fmaf(c.y, 0.25f, ty),
                    fmaf(c.z, 0.25f, tz), fmaf(c.w, 0.25f, tw));
}

__device__ __forceinline__ void vlerp(const float4& v0, const float4& v1, const float4& v2,
                                      float4& U0, float4& U1) {
    float tx = 0.75f * v1.x, ty = 0.75f * v1.y, tz = 0.75f * v1.z, tw = 0.75f * v1.w;
    U0 = make_float4(fmaf(v0.x, 0.25f, tx), fmaf(v0.y, 0.25f, ty),
                     fmaf(v0.z, 0.25f, tz), fmaf(v0.w, 0.25f, tw));
    U1 = make_float4(fmaf(v2.x, 0.25f, tx), fmaf(v2.y, 0.25f, ty),
                     fmaf(v2.z, 0.25f, tz), fmaf(v2.w, 0.25f, tw));
}

// out = 0.25*sum_k leaky(u_k) == 0.12625*sum(u) + 0.12375*sum(|u|)
// flattened to one FMUL-imm + 7 FFMA-imm per channel (all rt=1 forms;
// fabsf folds into FFMA source-abs modifiers)
__device__ __forceinline__ float corner1(float u00, float u01, float u10, float u11) {
    float r = u00 * 0.12625f;
    r = fmaf(u01, 0.12625f, r);
    r = fmaf(u10, 0.12625f, r);
    r = fmaf(u11, 0.12625f, r);
    r = fmaf(fabsf(u00), 0.12375f, r);
    r = fmaf(fabsf(u01), 0.12375f, r);
    r = fmaf(fabsf(u10), 0.12375f, r);
    r = fmaf(fabsf(u11), 0.12375f, r);
    return r;
}

__device__ __forceinline__ float4 corner_sum(const float4& u00, const float4& u01,
                                             const float4& u10, const float4& u11) {
    return make_float4(corner1(u00.x, u01.x, u10.x, u11.x),
                       corner1(u00.y, u01.y, u10.y, u11.y),
                       corner1(u00.z, u01.z, u10.z, u11.z),
                       corner1(u00.w, u01.w, u10.w, u11.w));
}

__global__ __launch_bounds__(256, 3)
void activation_filter_kernel(const float4* __restrict__ x, float4* __restrict__ out) {
    const int r0 = 2 * blockIdx.x;     // output row pair (r0, r0+1 = +WC4 elems)
    const int half = blockIdx.y;       // width half (0: cols 0..63, 1: 64..127)
    const int b  = blockIdx.z;
    const int tid = threadIdx.x;
    const int c4    = tid & 31;
    const int strip = tid >> 5;        // 0..7, warp-uniform
    const int j0    = half * 64 + strip * STRIP;

    const int im = (r0 > 0)         ? r0 - 1 : 0;      // row above r0 (clamped)
    const int iq = (r0 + 1 < H - 1) ? r0 + 2 : H - 1;  // row below r1 (clamped)

    const int img   = b * (H * WC4);
    const int basec = j0 * C4 + c4;
    const float4* __restrict__ pm = x + img + im * WC4 + basec;   // row im
    const float4* __restrict__ p0 = x + img + r0 * WC4 + basec;   // rows r0 (+WC4 -> r1)
    const float4* __restrict__ pq = x + img + iq * WC4 + basec;   // row iq
    float4* __restrict__ po = out + img + r0 * WC4 + basec;       // rows r0 (+WC4 -> r1)

    // window prologue: a = col j0-1 (clamped, warp-uniform), b = col j0
    const int offA = (j0 > 0) ? -C4 : 0;
    float4 a0 = pm[offA], a1 = p0[offA], a2 = p0[offA + WC4], a3 = pq[offA];
    float4 b0 = pm[0],    b1 = p0[0],    b2 = p0[WC4],        b3 = pq[0];

    #pragma unroll
    for (int s = 0; s < STRIP - 1; ++s) {
        // all loads first: 4 independent LDG.128
        float4 c0 = pm[C4];
        float4 c1 = p0[C4];
        float4 c2 = p0[C4 + WC4];
        float4 c3 = pq[C4];

        float4 L0, R0, L1, R1, L2, R2;
        hlerp(a0, b0, c0, L0, R0); a0 = b0; b0 = c0;
        hlerp(a1, b1, c1, L1, R1); a1 = b1; b1 = c1;
        hlerp(a2, b2, c2, L2, R2); a2 = b2; b2 = c2;

        // finish output row r0 before touching row 3 (liveness)
        {
            float4 u00, u10, u01, u11;
            vlerp(L0, L1, L2, u00, u10);
            vlerp(R0, R1, R2, u01, u11);
            __stcs(po, corner_sum(u00, u01, u10, u11));
        }

        float4 L3, R3;
        hlerp(a3, b3, c3, L3, R3); a3 = b3; b3 = c3;
        {
            float4 u00, u10, u01, u11;
            vlerp(L1, L2, L3, u00, u10);
            vlerp(R1, R2, R3, u01, u11);
            __stcs(po + WC4, corner_sum(u00, u01, u10, u11));
        }

        pm += C4; p0 += C4; pq += C4; po += C4;
    }

    // final column of the strip: only the rightmost strip clamps (warp-uniform)
    {
        float4 c0, c1, c2, c3;
        if (j0 + STRIP < W) {
            c0 = pm[C4]; c1 = p0[C4]; c2 = p0[C4 + WC4]; c3 = pq[C4];
        } else {
            c0 = b0; c1 = b1; c2 = b2; c3 = b3;
        }
        float4 L0, R0, L1, R1, L2, R2;
        hlerp(a0, b0, c0, L0, R0);
        hlerp(a1, b1, c1, L1, R1);
        hlerp(a2, b2, c2, L2, R2);
        {
            float4 u00, u10, u01, u11;
            vlerp(L0, L1, L2, u00, u10);
            vlerp(R0, R1, R2, u01, u11);
            __stcs(po, corner_sum(u00, u01, u10, u11));
        }
        float4 L3, R3;
        hlerp(a3, b3, c3, L3, R3);
        {
            float4 u00, u10, u01, u11;
            vlerp(L1, L2, L3, u00, u10);
            vlerp(R1, R2, R3, u01, u11);
            __stcs(po + WC4, corner_sum(u00, u01, u10, u11));
        }
    }
}

extern "C" void kernel_launch(void* const* d_in, const int* in_sizes, int n_in,
                              void* d_out, int out_size) {
    const float4* x = (const float4*)d_in[0];
    float4* out = (float4*)d_out;
    dim3 grid(H / 2, 2, 16);   // (row pair, width half, batch) = 2048 blocks
    activation_filter_kernel<<<grid, 256>>>(x, out);
}

// round 12
// speedup vs baseline: 1.0788x; 1.0252x over previous
#include <cuda_runtime.h>

// Fused bilinear 2x up -> leaky_relu(0.01) -> bilinear 0.5x down == 3x3 stencil.
// x, out: (16, 128, 128, 128) fp32 NHWC.
//
// R11 vs R10 (45.9us): vertical-first separable factorization.
// The 4 upsampled rows for an output row-pair are
//   V0=.25xa+.75xb  V1=.75xb+.25xc  V2=.25xb+.75xc  V3=.75xc+.25xd
// sharing t=.75xb and t=.75xc -> 6 ops/channel for the whole vertical stage
// (vs 12 ops/channel of horizontal lerps in the H-first order). Horizontal
// lerps then run on V rows; FFMA-imm corner chain from R10 kept. ~15% fewer
// instructions at identical loads and window registers (3 CTAs, 80 regs).

constexpr int H   = 128;
constexpr int W   = 128;
constexpr int C4  = 32;    // 128 channels / 4
constexpr int WC4 = W * C4;
constexpr int STRIP = 8;   // output columns per thread

// vertical stage: 4 x-rows -> 4 upsampled V-rows (t-sharing, FFMA-imm)
__device__ __forceinline__ void vquad(const float4& xa, const float4& xb,
                                      const float4& xc, const float4& xd,
                                      float4& V0, float4& V1, float4& V2, float4& V3) {
    {
        float t0 = 0.75f * xb.x, t1 = 0.75f * xc.x;
        V0.x = fmaf(xa.x, 0.25f, t0); V1.x = fmaf(xc.x, 0.25f, t0);
        V2.x = fmaf(xb.x, 0.25f, t1); V3.x = fmaf(xd.x, 0.25f, t1);
    }
    {
        float t0 = 0.75f * xb.y, t1 = 0.75f * xc.y;
        V0.y = fmaf(xa.y, 0.25f, t0); V1.y = fmaf(xc.y, 0.25f, t0);
        V2.y = fmaf(xb.y, 0.25f, t1); V3.y = fmaf(xd.y, 0.25f, t1);
    }
    {
        float t0 = 0.75f * xb.z, t1 = 0.75f * xc.z;
        V0.z = fmaf(xa.z, 0.25f, t0); V1.z = fmaf(xc.z, 0.25f, t0);
        V2.z = fmaf(xb.z, 0.25f, t1); V3.z = fmaf(xd.z, 0.25f, t1);
    }
    {
        float t0 = 0.75f * xb.w, t1 = 0.75f * xc.w;
        V0.w = fmaf(xa.w, 0.25f, t0); V1.w = fmaf(xc.w, 0.25f, t0);
        V2.w = fmaf(xb.w, 0.25f, t1); V3.w = fmaf(xd.w, 0.25f, t1);
    }
}

// horizontal stage on a V row: L = .25a+.75b ; R = .75b+.25c
__device__ __forceinline__ void hlerp(const float4& a, const float4& b, const float4& c,
                                      float4& L, float4& R) {
    float tx = 0.75f * b.x, ty = 0.75f * b.y, tz = 0.75f * b.z, tw = 0.75f * b.w;
    L = make_float4(fmaf(a.x, 0.25f, tx), fmaf(a.y, 0.25f, ty),
                    fmaf(a.z, 0.25f, tz), fmaf(a.w, 0.25f, tw));
    R = make_float4(fmaf(c.x, 0.25f, tx), fmaf(c.y, 0.25f, ty),
                    fmaf(c.z, 0.25f, tz), fmaf(c.w, 0.25f, tw));
}

// out = 0.25*sum_k leaky(u_k) == 0.12625*sum(u) + 0.12375*sum(|u|)
// one FMUL-imm + 7 FFMA-imm per channel; abs folds into FFMA modifiers
__device__ __forceinline__ float corner1(float u00, float u01, float u10, float u11) {
    float r = u00 * 0.12625f;
    r = fmaf(u01, 0.12625f, r);
    r = fmaf(u10, 0.12625f, r);
    r = fmaf(u11, 0.12625f, r);
    r = fmaf(fabsf(u00), 0.12375f, r);
    r = fmaf(fabsf(u01), 0.12375f, r);
    r = fmaf(fabsf(u10), 0.12375f, r);
    r = fmaf(fabsf(u11), 0.12375f, r);
    return r;
}

__device__ __forceinline__ float4 corner_sum(const float4& u00, const float4& u01,
                                             const float4& u10, const float4& u11) {
    return make_float4(corner1(u00.x, u01.x, u10.x, u11.x),
                       corner1(u00.y, u01.y, u10.y, u11.y),
                       corner1(u00.z, u01.z, u10.z, u11.z),
                       corner1(u00.w, u01.w, u10.w, u11.w));
}

__global__ __launch_bounds__(256, 3)
void activation_filter_kernel(const float4* __restrict__ x, float4* __restrict__ out) {
    const int r0 = 2 * blockIdx.x;     // output row pair (r0, r0+1)
    const int half = blockIdx.y;       // width half (0: cols 0..63, 1: 64..127)
    const int b  = blockIdx.z;
    const int tid = threadIdx.x;
    const int c4    = tid & 31;
    const int strip = tid >> 5;        // 0..7, warp-uniform
    const int j0    = half * 64 + strip * STRIP;

    const int im = (r0 > 0)         ? r0 - 1 : 0;      // row above r0 (clamped)
    const int iq = (r0 + 1 < H - 1) ? r0 + 2 : H - 1;  // row below r1 (clamped)

    const int img   = b * (H * WC4);
    const int basec = j0 * C4 + c4;
    const float4* __restrict__ pa = x + img + im * WC4 + basec;   // row im
    const float4* __restrict__ pb = x + img + r0 * WC4 + basec;   // rows r0 (+WC4 -> r1)
    const float4* __restrict__ pd = x + img + iq * WC4 + basec;   // row iq
    float4* __restrict__ po = out + img + r0 * WC4 + basec;       // rows r0 (+WC4 -> r1)

    // prologue: V for col j0-1 (clamped, warp-uniform) and col j0
    const int offA = (j0 > 0) ? -C4 : 0;
    float4 Vp0, Vp1, Vp2, Vp3, Vc0, Vc1, Vc2, Vc3;
    {
        float4 xa = pa[offA], xb = pb[offA], xc = pb[offA + WC4], xd = pd[offA];
        vquad(xa, xb, xc, xd, Vp0, Vp1, Vp2, Vp3);
    }
    {
        float4 xa = pa[0], xb = pb[0], xc = pb[WC4], xd = pd[0];
        vquad(xa, xb, xc, xd, Vc0, Vc1, Vc2, Vc3);
    }

    #pragma unroll
    for (int s = 0; s < STRIP - 1; ++s) {
        // all loads first: 4 independent LDG.128 (col j+1)
        float4 xa = pa[C4];
        float4 xb = pb[C4];
        float4 xc = pb[C4 + WC4];
        float4 xd = pd[C4];

        float4 Vn0, Vn1, Vn2, Vn3;
        vquad(xa, xb, xc, xd, Vn0, Vn1, Vn2, Vn3);

        // output row r0 (up-rows V0, V1), finished before touching V2/V3 u's
        {
            float4 uL0, uR0, uL1, uR1;
            hlerp(Vp0, Vc0, Vn0, uL0, uR0);
            hlerp(Vp1, Vc1, Vn1, uL1, uR1);
            __stcs(po, corner_sum(uL0, uR0, uL1, uR1));
        }
        // output row r1 (up-rows V2, V3)
        {
            float4 uL2, uR2, uL3, uR3;
            hlerp(Vp2, Vc2, Vn2, uL2, uR2);
            hlerp(Vp3, Vc3, Vn3, uL3, uR3);
            __stcs(po + WC4, corner_sum(uL2, uR2, uL3, uR3));
        }

        // slide V window
        Vp0 = Vc0; Vp1 = Vc1; Vp2 = Vc2; Vp3 = Vc3;
        Vc0 = Vn0; Vc1 = Vn1; Vc2 = Vn2; Vc3 = Vn3;
        pa += C4; pb += C4; pd += C4; po += C4;
    }

    // final column: only the rightmost strip clamps (warp-uniform); V is
    // linear so clamped x columns imply Vn = Vc exactly.
    {
        float4 Vn0, Vn1, Vn2, Vn3;
        if (j0 + STRIP < W) {
            float4 xa = pa[C4], xb = pb[C4], xc = pb[C4 + WC4], xd = pd[C4];
            vquad(xa, xb, xc, xd, Vn0, Vn1, Vn2, Vn3);
        } else {
            Vn0 = Vc0; Vn1 = Vc1; Vn2 = Vc2; Vn3 = Vc3;
        }
        {
            float4 uL0, uR0, uL1, uR1;
            hlerp(Vp0, Vc0, Vn0, uL0, uR0);
            hlerp(Vp1, Vc1, Vn1, uL1, uR1);
            __stcs(po, corner_sum(uL0, uR0, uL1, uR1));
        }
        {
            float4 uL2, uR2, uL3, uR3;
            hlerp(Vp2, Vc2, Vn2, uL2, uR2);
            hlerp(Vp3, Vc3, Vn3, uL3, uR3);
            __stcs(po + WC4, corner_sum(uL2, uR2, uL3, uR3));
        }
    }
}

extern "C" void kernel_launch(void* const* d_in, const int* in_sizes, int n_in,
                              void* d_out, int out_size) {
    const float4* x = (const float4*)d_in[0];
    float4* out = (float4*)d_out;
    dim3 grid(H / 2, 2, 16);   // (row pair, width half, batch) = 2048 blocks
    activation_filter_kernel<<<grid, 256>>>(x, out);
}

// round 13
// speedup vs baseline: 1.0848x; 1.0056x over previous
#include <cuda_runtime.h>
#include <cuda_pipeline.h>

// Fused bilinear 2x up -> leaky_relu(0.01) -> bilinear 0.5x down == 3x3 stencil.
// x, out: (16, 128, 128, 128) fp32 NHWC.
//
// R12 vs R11 (45.8us, latency-bound: loads consumed 0 instr after issue):
//  - cp.async (LDGSTS) 1-column-ahead pipeline into smem; per-thread
//    commit/wait_prior only (data is thread-private -> no block barriers)
//  - load->use distance = 1 full iteration of compute + 24-warp overlap
//  - zero extra persistent registers: keeps the proven 3-CTA/80-reg point
//  - smem [buf][row][tid]: conflict-free 16B lanes; 32KB/CTA, 96KB/SM

constexpr int H   = 128;
constexpr int W   = 128;
constexpr int C4  = 32;    // 128 channels / 4
constexpr int WC4 = W * C4;
constexpr int STRIP = 8;   // output columns per thread

// vertical stage: 4 x-rows -> 4 upsampled V-rows (t-sharing, FFMA-imm)
__device__ __forceinline__ void vquad(const float4& xa, const float4& xb,
                                      const float4& xc, const float4& xd,
                                      float4& V0, float4& V1, float4& V2, float4& V3) {
    {
        float t0 = 0.75f * xb.x, t1 = 0.75f * xc.x;
        V0.x = fmaf(xa.x, 0.25f, t0); V1.x = fmaf(xc.x, 0.25f, t0);
        V2.x = fmaf(xb.x, 0.25f, t1); V3.x = fmaf(xd.x, 0.25f, t1);
    }
    {
        float t0 = 0.75f * xb.y, t1 = 0.75f * xc.y;
        V0.y = fmaf(xa.y, 0.25f, t0); V1.y = fmaf(xc.y, 0.25f, t0);
        V2.y = fmaf(xb.y, 0.25f, t1); V3.y = fmaf(xd.y, 0.25f, t1);
    }
    {
        float t0 = 0.75f * xb.z, t1 = 0.75f * xc.z;
        V0.z = fmaf(xa.z, 0.25f, t0); V1.z = fmaf(xc.z, 0.25f, t0);
        V2.z = fmaf(xb.z, 0.25f, t1); V3.z = fmaf(xd.z, 0.25f, t1);
    }
    {
        float t0 = 0.75f * xb.w, t1 = 0.75f * xc.w;
        V0.w = fmaf(xa.w, 0.25f, t0); V1.w = fmaf(xc.w, 0.25f, t0);
        V2.w = fmaf(xb.w, 0.25f, t1); V3.w = fmaf(xd.w, 0.25f, t1);
    }
}

// horizontal stage on a V row: L = .25a+.75b ; R = .75b+.25c
__device__ __forceinline__ void hlerp(const float4& a, const float4& b, const float4& c,
                                      float4& L, float4& R) {
    float tx = 0.75f * b.x, ty = 0.75f * b.y, tz = 0.75f * b.z, tw = 0.75f * b.w;
    L = make_float4(fmaf(a.x, 0.25f, tx), fmaf(a.y, 0.25f, ty),
                    fmaf(a.z, 0.25f, tz), fmaf(a.w, 0.25f, tw));
    R = make_float4(fmaf(c.x, 0.25f, tx), fmaf(c.y, 0.25f, ty),
                    fmaf(c.z, 0.25f, tz), fmaf(c.w, 0.25f, tw));
}

// out = 0.25*sum_k leaky(u_k) == 0.12625*sum(u) + 0.12375*sum(|u|)
__device__ __forceinline__ float corner1(float u00, float u01, float u10, float u11) {
    float r = u00 * 0.12625f;
    r = fmaf(u01, 0.12625f, r);
    r = fmaf(u10, 0.12625f, r);
    r = fmaf(u11, 0.12625f, r);
    r = fmaf(fabsf(u00), 0.12375f, r);
    r = fmaf(fabsf(u01), 0.12375f, r);
    r = fmaf(fabsf(u10), 0.12375f, r);
    r = fmaf(fabsf(u11), 0.12375f, r);
    return r;
}

__device__ __forceinline__ float4 corner_sum(const float4& u00, const float4& u01,
                                             const float4& u10, const float4& u11) {
    return make_float4(corner1(u00.x, u01.x, u10.x, u11.x),
                       corner1(u00.y, u01.y, u10.y, u11.y),
                       corner1(u00.z, u01.z, u10.z, u11.z),
                       corner1(u00.w, u01.w, u10.w, u11.w));
}

__global__ __launch_bounds__(256, 3)
void activation_filter_kernel(const float4* __restrict__ x, float4* __restrict__ out) {
    __shared__ float4 stage[2][4][256];   // [buf][row][tid]: 32 KB

    const int r0 = 2 * blockIdx.x;     // output row pair (r0, r0+1)
    const int half = blockIdx.y;       // width half
    const int b  = blockIdx.z;
    const int tid = threadIdx.x;
    const int c4    = tid & 31;
    const int strip = tid >> 5;        // warp-uniform
    const int j0    = half * 64 + strip * STRIP;

    const int im = (r0 > 0)         ? r0 - 1 : 0;
    const int iq = (r0 + 1 < H - 1) ? r0 + 2 : H - 1;

    const int img   = b * (H * WC4);
    const int basec = j0 * C4 + c4;
    const float4* __restrict__ pa = x + img + im * WC4 + basec;   // row im
    const float4* __restrict__ pb = x + img + r0 * WC4 + basec;   // rows r0/r1
    const float4* __restrict__ pd = x + img + iq * WC4 + basec;   // row iq
    float4* __restrict__ po = out + img + r0 * WC4 + basec;

    // prologue: direct loads for cols j0-1 (clamped) and j0 -> Vp, Vc
    const int offA = (j0 > 0) ? -C4 : 0;
    float4 Vp0, Vp1, Vp2, Vp3, Vc0, Vc1, Vc2, Vc3;
    {
        float4 xa = pa[offA], xb = pb[offA], xc = pb[offA + WC4], xd = pd[offA];
        float4 ya = pa[0],    yb = pb[0],    yc = pb[WC4],        yd = pd[0];
        vquad(xa, xb, xc, xd, Vp0, Vp1, Vp2, Vp3);
        vquad(ya, yb, yc, yd, Vc0, Vc1, Vc2, Vc3);
    }
    // async prefetch col j0+1 -> buf 0
    __pipeline_memcpy_async(&stage[0][0][tid], pa + C4, 16);
    __pipeline_memcpy_async(&stage[0][1][tid], pb + C4, 16);
    __pipeline_memcpy_async(&stage[0][2][tid], pb + C4 + WC4, 16);
    __pipeline_memcpy_async(&stage[0][3][tid], pd + C4, 16);
    __pipeline_commit();

    #pragma unroll
    for (int s = 0; s < STRIP - 1; ++s) {
        // issue prefetch of col j0+s+2 into the other buffer (warp-uniform guard)
        const int nb = (s + 1) & 1;
        if (j0 + s + 2 < W) {
            __pipeline_memcpy_async(&stage[nb][0][tid], pa + 2 * C4, 16);
            __pipeline_memcpy_async(&stage[nb][1][tid], pb + 2 * C4, 16);
            __pipeline_memcpy_async(&stage[nb][2][tid], pb + 2 * C4 + WC4, 16);
            __pipeline_memcpy_async(&stage[nb][3][tid], pd + 2 * C4, 16);
        }
        __pipeline_commit();
        __pipeline_wait_prior(1);          // col j0+s+1 resident in buf s&1

        const int cb = s & 1;
        float4 xa = stage[cb][0][tid];
        float4 xb = stage[cb][1][tid];
        float4 xc = stage[cb][2][tid];
        float4 xd = stage[cb][3][tid];

        float4 Vn0, Vn1, Vn2, Vn3;
        vquad(xa, xb, xc, xd, Vn0, Vn1, Vn2, Vn3);

        {   // output row r0 (up-rows V0, V1)
            float4 uL0, uR0, uL1, uR1;
            hlerp(Vp0, Vc0, Vn0, uL0, uR0);
            hlerp(Vp1, Vc1, Vn1, uL1, uR1);
            __stcs(po, corner_sum(uL0, uR0, uL1, uR1));
        }
        {   // output row r1 (up-rows V2, V3)
            float4 uL2, uR2, uL3, uR3;
            hlerp(Vp2, Vc2, Vn2, uL2, uR2);
            hlerp(Vp3, Vc3, Vn3, uL3, uR3);
            __stcs(po + WC4, corner_sum(uL2, uR2, uL3, uR3));
        }

        Vp0 = Vc0; Vp1 = Vc1; Vp2 = Vc2; Vp3 = Vc3;
        Vc0 = Vn0; Vc1 = Vn1; Vc2 = Vn2; Vc3 = Vn3;
        pa += C4; pb += C4; pd += C4; po += C4;
    }

    // final column j0+7: needs col j0+8 (clamped only on the rightmost strip;
    // V is linear so clamped x columns imply Vn = Vc exactly)
    {
        float4 Vn0, Vn1, Vn2, Vn3;
        if (j0 + STRIP < W) {
            __pipeline_wait_prior(0);      // col j0+8 resident in buf 1
            float4 xa = stage[1][0][tid];
            float4 xb = stage[1][1][tid];
            float4 xc = stage[1][2][tid];
            float4 xd = stage[1][3][tid];
            vquad(xa, xb, xc, xd, Vn0, Vn1, Vn2, Vn3);
        } else {
            Vn0 = Vc0; Vn1 = Vc1; Vn2 = Vc2; Vn3 = Vc3;
        }
        {
            float4 uL0, uR0, uL1, uR1;
            hlerp(Vp0, Vc0, Vn0, uL0, uR0);
            hlerp(Vp1, Vc1, Vn1, uL1, uR1);
            __stcs(po, corner_sum(uL0, uR0, uL1, uR1));
        }
        {
            float4 uL2, uR2, uL3, uR3;
            hlerp(Vp2, Vc2, Vn2, uL2, uR2);
            hlerp(Vp3, Vc3, Vn3, uL3, uR3);
            __stcs(po + WC4, corner_sum(uL2, uR2, uL3, uR3));
        }
    }
}

extern "C" void kernel_launch(void* const* d_in, const int* in_sizes, int n_in,
                              void* d_out, int out_size) {
    const float4* x = (const float4*)d_in[0];
    float4* out = (float4*)d_out;
    dim3 grid(H / 2, 2, 16);   // (row pair, width half, batch) = 2048 blocks
    activation_filter_kernel<<<grid, 256>>>(x, out);
}

// round 14
// speedup vs baseline: 1.2312x; 1.1349x over previous
#include <cuda_runtime.h>

// Fused bilinear 2x up -> leaky_relu(0.01) -> bilinear 0.5x down == 3x3 stencil.
// x, out: (16, 128, 128, 128) fp32 NHWC.
//
// R13 = R11 (best kernel: 45.8us; V-first factorization, FFMA-imm corner,
// 3 CTAs/80 regs) + prologue L2 prefetch of the whole strip (cols +1..+7,
// 4 rows = 28 prefetch.global.L2, no destination regs, no smem, no sync).
// R12 proved latency is the binder (issue 40->70% when hidden) but its
// cp.async machinery cost more than it saved; prefetch is the free version.

constexpr int H   = 128;
constexpr int W   = 128;
constexpr int C4  = 32;    // 128 channels / 4
constexpr int WC4 = W * C4;
constexpr int STRIP = 8;   // output columns per thread

__device__ __forceinline__ void prefetch_l2(const void* p) {
    asm volatile("prefetch.global.L2 [%0];" :: "l"(p));
}

// vertical stage: 4 x-rows -> 4 upsampled V-rows (t-sharing, FFMA-imm)
__device__ __forceinline__ void vquad(const float4& xa, const float4& xb,
                                      const float4& xc, const float4& xd,
                                      float4& V0, float4& V1, float4& V2, float4& V3) {
    {
        float t0 = 0.75f * xb.x, t1 = 0.75f * xc.x;
        V0.x = fmaf(xa.x, 0.25f, t0); V1.x = fmaf(xc.x, 0.25f, t0);
        V2.x = fmaf(xb.x, 0.25f, t1); V3.x = fmaf(xd.x, 0.25f, t1);
    }
    {
        float t0 = 0.75f * xb.y, t1 = 0.75f * xc.y;
        V0.y = fmaf(xa.y, 0.25f, t0); V1.y = fmaf(xc.y, 0.25f, t0);
        V2.y = fmaf(xb.y, 0.25f, t1); V3.y = fmaf(xd.y, 0.25f, t1);
    }
    {
        float t0 = 0.75f * xb.z, t1 = 0.75f * xc.z;
        V0.z = fmaf(xa.z, 0.25f, t0); V1.z = fmaf(xc.z, 0.25f, t0);
        V2.z = fmaf(xb.z, 0.25f, t1); V3.z = fmaf(xd.z, 0.25f, t1);
    }
    {
        float t0 = 0.75f * xb.w, t1 = 0.75f * xc.w;
        V0.w = fmaf(xa.w, 0.25f, t0); V1.w = fmaf(xc.w, 0.25f, t0);
        V2.w = fmaf(xb.w, 0.25f, t1); V3.w = fmaf(xd.w, 0.25f, t1);
    }
}

// horizontal stage on a V row: L = .25a+.75b ; R = .75b+.25c
__device__ __forceinline__ void hlerp(const float4& a, const float4& b, const float4& c,
                                      float4& L, float4& R) {
    float tx = 0.75f * b.x, ty = 0.75f * b.y, tz = 0.75f * b.z, tw = 0.75f * b.w;
    L = make_float4(fmaf(a.x, 0.25f, tx), fmaf(a.y, 0.25f, ty),
                    fmaf(a.z, 0.25f, tz), fmaf(a.w, 0.25f, tw));
    R = make_float4(fmaf(c.x, 0.25f, tx), fmaf(c.y, 0.25f, ty),
                    fmaf(c.z, 0.25f, tz), fmaf(c.w, 0.25f, tw));
}

// out = 0.25*sum_k leaky(u_k) == 0.12625*sum(u) + 0.12375*sum(|u|)
// one FMUL-imm + 7 FFMA-imm per channel; abs folds into FFMA modifiers
__device__ __forceinline__ float corner1(float u00, float u01, float u10, float u11) {
    float r = u00 * 0.12625f;
    r = fmaf(u01, 0.12625f, r);
    r = fmaf(u10, 0.12625f, r);
    r = fmaf(u11, 0.12625f, r);
    r = fmaf(fabsf(u00), 0.12375f, r);
    r = fmaf(fabsf(u01), 0.12375f, r);
    r = fmaf(fabsf(u10), 0.12375f, r);
    r = fmaf(fabsf(u11), 0.12375f, r);
    return r;
}

__device__ __forceinline__ float4 corner_sum(const float4& u00, const float4& u01,
                                             const float4& u10, const float4& u11) {
    return make_float4(corner1(u00.x, u01.x, u10.x, u11.x),
                       corner1(u00.y, u01.y, u10.y, u11.y),
                       corner1(u00.z, u01.z, u10.z, u11.z),
                       corner1(u00.w, u01.w, u10.w, u11.w));
}

__global__ __launch_bounds__(256, 3)
void activation_filter_kernel(const float4* __restrict__ x, float4* __restrict__ out) {
    const int r0 = 2 * blockIdx.x;     // output row pair (r0, r0+1)
    const int half = blockIdx.y;       // width half (0: cols 0..63, 1: 64..127)
    const int b  = blockIdx.z;
    const int tid = threadIdx.x;
    const int c4    = tid & 31;
    const int strip = tid >> 5;        // 0..7, warp-uniform
    const int j0    = half * 64 + strip * STRIP;

    const int im = (r0 > 0)         ? r0 - 1 : 0;      // row above r0 (clamped)
    const int iq = (r0 + 1 < H - 1) ? r0 + 2 : H - 1;  // row below r1 (clamped)

    const int img   = b * (H * WC4);
    const int basec = j0 * C4 + c4;
    const float4* __restrict__ pa = x + img + im * WC4 + basec;   // row im
    const float4* __restrict__ pb = x + img + r0 * WC4 + basec;   // rows r0 (+WC4 -> r1)
    const float4* __restrict__ pd = x + img + iq * WC4 + basec;   // row iq
    float4* __restrict__ po = out + img + r0 * WC4 + basec;       // rows r0 (+WC4 -> r1)

    // prologue: direct loads for cols j0-1 (clamped, warp-uniform) and j0
    const int offA = (j0 > 0) ? -C4 : 0;
    float4 xa0 = pa[offA], xb0 = pb[offA], xc0 = pb[offA + WC4], xd0 = pd[offA];
    float4 ya0 = pa[0],    yb0 = pb[0],    yc0 = pb[WC4],        yd0 = pd[0];

    // L2-prefetch the rest of the strip (cols +1..+7 all in-bounds: j0max+7=127)
    // in the shadow of the prologue loads. No regs, no smem, no sync.
    #pragma unroll
    for (int t = 1; t <= STRIP - 1; ++t) {
        prefetch_l2(pa + t * C4);
        prefetch_l2(pb + t * C4);
        prefetch_l2(pb + t * C4 + WC4);
        prefetch_l2(pd + t * C4);
    }

    float4 Vp0, Vp1, Vp2, Vp3, Vc0, Vc1, Vc2, Vc3;
    vquad(xa0, xb0, xc0, xd0, Vp0, Vp1, Vp2, Vp3);
    vquad(ya0, yb0, yc0, yd0, Vc0, Vc1, Vc2, Vc3);

    #pragma unroll
    for (int s = 0; s < STRIP - 1; ++s) {
        // all loads first: 4 independent LDG.128 (col j+1, L2-warm)
        float4 xa = pa[C4];
        float4 xb = pb[C4];
        float4 xc = pb[C4 + WC4];
        float4 xd = pd[C4];

        float4 Vn0, Vn1, Vn2, Vn3;
        vquad(xa, xb, xc, xd, Vn0, Vn1, Vn2, Vn3);

        {   // output row r0 (up-rows V0, V1)
            float4 uL0, uR0, uL1, uR1;
            hlerp(Vp0, Vc0, Vn0, uL0, uR0);
            hlerp(Vp1, Vc1, Vn1, uL1, uR1);
            __stcs(po, corner_sum(uL0, uR0, uL1, uR1));
        }
        {   // output row r1 (up-rows V2, V3)
            float4 uL2, uR2, uL3, uR3;
            hlerp(Vp2, Vc2, Vn2, uL2, uR2);
            hlerp(Vp3, Vc3, Vn3, uL3, uR3);
            __stcs(po + WC4, corner_sum(uL2, uR2, uL3, uR3));
        }

        // slide V window
        Vp0 = Vc0; Vp1 = Vc1; Vp2 = Vc2; Vp3 = Vc3;
        Vc0 = Vn0; Vc1 = Vn1; Vc2 = Vn2; Vc3 = Vn3;
        pa += C4; pb += C4; pd += C4; po += C4;
    }

    // final column: only the rightmost strip clamps (warp-uniform); V is
    // linear so clamped x columns imply Vn = Vc exactly.
    {
        float4 Vn0, Vn1, Vn2, Vn3;
        if (j0 + STRIP < W) {
            float4 xa = pa[C4], xb = pb[C4], xc = pb[C4 + WC4], xd = pd[C4];
            vquad(xa, xb, xc, xd, Vn0, Vn1, Vn2, Vn3);
        } else {
            Vn0 = Vc0; Vn1 = Vc1; Vn2 = Vc2; Vn3 = Vc3;
        }
        {
            float4 uL0, uR0, uL1, uR1;
            hlerp(Vp0, Vc0, Vn0, uL0, uR0);
            hlerp(Vp1, Vc1, Vn1, uL1, uR1);
            __stcs(po, corner_sum(uL0, uR0, uL1, uR1));
        }
        {
            float4 uL2, uR2, uL3, uR3;
            hlerp(Vp2, Vc2, Vn2, uL2, uR2);
            hlerp(Vp3, Vc3, Vn3, uL3, uR3);
            __stcs(po + WC4, corner_sum(uL2, uR2, uL3, uR3));
        }
    }
}

extern "C" void kernel_launch(void* const* d_in, const int* in_sizes, int n_in,
                              void* d_out, int out_size) {
    const float4* x = (const float4*)d_in[0];
    float4* out = (float4*)d_out;
    dim3 grid(H / 2, 2, 16);   // (row pair, width half, batch) = 2048 blocks
    activation_filter_kernel<<<grid, 256>>>(x, out);
}